// round 2
// baseline (speedup 1.0000x reference)
#include <cuda_runtime.h>
#include <math.h>

#define D_MODEL 1024
#define L_SEQ   2048
#define BATCH   2
#define NHEAD   16
#define HDIM    64
#define M_TOT   (BATCH * L_SEQ)   // 4096

// Scratch for Q/K/V projections ([B, L, D_MODEL] row-major), 16 MB each.
__device__ float g_q[M_TOT * D_MODEL];
__device__ float g_k[M_TOT * D_MODEL];
__device__ float g_v[M_TOT * D_MODEL];

// ---------------------------------------------------------------------------
// Kernel 1: QKV projection GEMMs.  C[4096,1024] = A[4096,1024] @ W[1024,1024]
// blockIdx.z selects which of the three projections.
// 128x128 block tile, BK=8, 256 threads, 8x8 register microtile.
// ---------------------------------------------------------------------------
__global__ __launch_bounds__(256) void proj_gemm(
    const float* __restrict__ Xq, const float* __restrict__ Xk, const float* __restrict__ Xv,
    const float* __restrict__ Wq, const float* __restrict__ Wk, const float* __restrict__ Wv)
{
    const int GN = D_MODEL, GK = D_MODEL;

    const float* A;
    const float* B;
    float* C;
    if (blockIdx.z == 0)      { A = Xq; B = Wq; C = g_q; }
    else if (blockIdx.z == 1) { A = Xk; B = Wk; C = g_k; }
    else                      { A = Xv; B = Wv; C = g_v; }

    __shared__ float As[8][128];   // transposed A tile: As[k][m]
    __shared__ float Bs[8][128];   // Bs[k][n]

    const int tid  = threadIdx.x;
    const int brow = blockIdx.y * 128;
    const int bcol = blockIdx.x * 128;

    // A tile load: 128 rows x 8 k, one float4 per thread
    const int aRow = tid >> 1;          // 0..127
    const int aCol = (tid & 1) * 4;     // 0 or 4
    // B tile load: 8 k x 128 cols, one float4 per thread
    const int bRow = tid >> 5;          // 0..7
    const int bCol = (tid & 31) * 4;    // 0..124

    const int ty = tid >> 4;            // 0..15  (row microtile group)
    const int tx = tid & 15;            // 0..15  (col microtile group)

    float acc[8][8];
    #pragma unroll
    for (int i = 0; i < 8; i++)
        #pragma unroll
        for (int j = 0; j < 8; j++) acc[i][j] = 0.f;

    for (int k0 = 0; k0 < GK; k0 += 8) {
        float4 a4 = *(const float4*)&A[(brow + aRow) * GK + k0 + aCol];
        As[aCol + 0][aRow] = a4.x;
        As[aCol + 1][aRow] = a4.y;
        As[aCol + 2][aRow] = a4.z;
        As[aCol + 3][aRow] = a4.w;
        *(float4*)&Bs[bRow][bCol] = *(const float4*)&B[(k0 + bRow) * GN + bcol + bCol];
        __syncthreads();

        #pragma unroll
        for (int k = 0; k < 8; k++) {
            float ar[8], br[8];
            *(float4*)&ar[0] = *(const float4*)&As[k][ty * 8];
            *(float4*)&ar[4] = *(const float4*)&As[k][ty * 8 + 4];
            *(float4*)&br[0] = *(const float4*)&Bs[k][tx * 8];
            *(float4*)&br[4] = *(const float4*)&Bs[k][tx * 8 + 4];
            #pragma unroll
            for (int i = 0; i < 8; i++)
                #pragma unroll
                for (int j = 0; j < 8; j++)
                    acc[i][j] += ar[i] * br[j];
        }
        __syncthreads();
    }

    #pragma unroll
    for (int i = 0; i < 8; i++) {
        int r = brow + ty * 8 + i;
        *(float4*)&C[r * GN + bcol + tx * 8]     = make_float4(acc[i][0], acc[i][1], acc[i][2], acc[i][3]);
        *(float4*)&C[r * GN + bcol + tx * 8 + 4] = make_float4(acc[i][4], acc[i][5], acc[i][6], acc[i][7]);
    }
}

// ---------------------------------------------------------------------------
// Kernel 2: flash attention per (q-tile of 64, head, batch).
// Online softmax, kv loop bounded by v_len (exactly equivalent to the -1e12
// additive mask: exp underflows to 0 in fp32). Query rows >= q_len output 0.
// 256 threads: thread (rg, cg) owns rows rg*4..+3 and cols {cg + 16*ci}.
// ---------------------------------------------------------------------------
#define PAD 68
#define SMEM_FLOATS (3 * 64 * PAD)
#define SMEM_BYTES  (SMEM_FLOATS * 4)

__global__ __launch_bounds__(256) void flash_attn(
    const int* __restrict__ q_len, const int* __restrict__ v_len,
    float* __restrict__ out)
{
    const int qt = blockIdx.x;   // 0..31
    const int h  = blockIdx.y;   // 0..15
    const int b  = blockIdx.z;   // 0..1
    const int q0 = qt * 64;
    const int tid = threadIdx.x;

    const int qlen = q_len[b];
    const int klen = v_len[b];

    float* outp = out + (b * L_SEQ + q0) * D_MODEL + h * HDIM;

    if (q0 >= qlen) {
        // whole q tile masked: write zeros
        for (int idx = tid; idx < 64 * 16; idx += 256) {
            int r = idx >> 4, c4 = (idx & 15) << 2;
            *(float4*)&outp[r * D_MODEL + c4] = make_float4(0.f, 0.f, 0.f, 0.f);
        }
        return;
    }

    extern __shared__ float sm[];
    float* Qs  = sm;                 // 64 x PAD (Q rows, scaled)
    float* KVs = sm + 64 * PAD;      // 64 x PAD (K rows, then V transposed [d][j])
    float* Ps  = sm + 2 * 64 * PAD;  // 64 x PAD (probabilities)

    const float* qp = g_q + (b * L_SEQ + q0) * D_MODEL + h * HDIM;
    const float* kp = g_k + (b * L_SEQ) * D_MODEL + h * HDIM;
    const float* vp = g_v + (b * L_SEQ) * D_MODEL + h * HDIM;

    // Load and scale Q tile (64x64)
    for (int idx = tid; idx < 64 * 16; idx += 256) {
        int r = idx >> 4, c4 = (idx & 15) << 2;
        float4 v4 = *(const float4*)&qp[r * D_MODEL + c4];
        v4.x *= 0.125f; v4.y *= 0.125f; v4.z *= 0.125f; v4.w *= 0.125f;
        *(float4*)&Qs[r * PAD + c4] = v4;
    }

    const int rg = tid >> 4;   // 0..15
    const int cg = tid & 15;   // 0..15

    float m_i[4], l_i[4], o[4][4];
    #pragma unroll
    for (int i = 0; i < 4; i++) {
        m_i[i] = -1e30f; l_i[i] = 0.f;
        #pragma unroll
        for (int j = 0; j < 4; j++) o[i][j] = 0.f;
    }

    const int n_kv = (klen + 63) >> 6;
    for (int kt = 0; kt < n_kv; kt++) {
        const int k0 = kt << 6;

        // Load K tile (row-major [j][d])
        for (int idx = tid; idx < 64 * 16; idx += 256) {
            int r = idx >> 4, c4 = (idx & 15) << 2;
            *(float4*)&KVs[r * PAD + c4] = *(const float4*)&kp[(k0 + r) * D_MODEL + c4];
        }
        __syncthreads();

        // S = Q K^T for this thread's 4x4 patch
        float s[4][4];
        #pragma unroll
        for (int i = 0; i < 4; i++)
            #pragma unroll
            for (int j = 0; j < 4; j++) s[i][j] = 0.f;

        #pragma unroll
        for (int d4 = 0; d4 < 16; d4++) {
            float4 q4[4], k4[4];
            #pragma unroll
            for (int ri = 0; ri < 4; ri++)
                q4[ri] = *(const float4*)&Qs[(rg * 4 + ri) * PAD + d4 * 4];
            #pragma unroll
            for (int ci = 0; ci < 4; ci++)
                k4[ci] = *(const float4*)&KVs[(cg + ci * 16) * PAD + d4 * 4];
            #pragma unroll
            for (int ri = 0; ri < 4; ri++)
                #pragma unroll
                for (int ci = 0; ci < 4; ci++)
                    s[ri][ci] += q4[ri].x * k4[ci].x + q4[ri].y * k4[ci].y
                               + q4[ri].z * k4[ci].z + q4[ri].w * k4[ci].w;
        }

        // key mask for the boundary tile
        #pragma unroll
        for (int ci = 0; ci < 4; ci++) {
            if (k0 + cg + ci * 16 >= klen) {
                #pragma unroll
                for (int ri = 0; ri < 4; ri++) s[ri][ci] = -1e30f;
            }
        }

        // online softmax per row (16 threads per row cooperate via shfl)
        #pragma unroll
        for (int ri = 0; ri < 4; ri++) {
            float mx = fmaxf(fmaxf(s[ri][0], s[ri][1]), fmaxf(s[ri][2], s[ri][3]));
            #pragma unroll
            for (int off = 1; off < 16; off <<= 1)
                mx = fmaxf(mx, __shfl_xor_sync(0xffffffffu, mx, off));

            float m_new = fmaxf(m_i[ri], mx);
            float scale = __expf(m_i[ri] - m_new);

            float rsum = 0.f;
            #pragma unroll
            for (int ci = 0; ci < 4; ci++) {
                float p = __expf(s[ri][ci] - m_new);
                rsum += p;
                Ps[(rg * 4 + ri) * PAD + cg + ci * 16] = p;
            }
            #pragma unroll
            for (int off = 1; off < 16; off <<= 1)
                rsum += __shfl_xor_sync(0xffffffffu, rsum, off);

            l_i[ri] = l_i[ri] * scale + rsum;
            m_i[ri] = m_new;
            #pragma unroll
            for (int ci = 0; ci < 4; ci++) o[ri][ci] *= scale;
        }
        __syncthreads();  // done reading K tile; Ps visible

        // Load V tile transposed into KVs: KVs[d][j]
        for (int idx = tid; idx < 64 * 16; idx += 256) {
            int r = idx >> 4, c4 = (idx & 15) << 2;
            float4 v4 = *(const float4*)&vp[(k0 + r) * D_MODEL + c4];
            KVs[(c4 + 0) * PAD + r] = v4.x;
            KVs[(c4 + 1) * PAD + r] = v4.y;
            KVs[(c4 + 2) * PAD + r] = v4.z;
            KVs[(c4 + 3) * PAD + r] = v4.w;
        }
        __syncthreads();

        // O += P @ V  (vectorized over j via the transposed V)
        #pragma unroll
        for (int j4 = 0; j4 < 16; j4++) {
            float4 p4[4], v4[4];
            #pragma unroll
            for (int ri = 0; ri < 4; ri++)
                p4[ri] = *(const float4*)&Ps[(rg * 4 + ri) * PAD + j4 * 4];
            #pragma unroll
            for (int ci = 0; ci < 4; ci++)
                v4[ci] = *(const float4*)&KVs[(cg + ci * 16) * PAD + j4 * 4];
            #pragma unroll
            for (int ri = 0; ri < 4; ri++)
                #pragma unroll
                for (int ci = 0; ci < 4; ci++)
                    o[ri][ci] += p4[ri].x * v4[ci].x + p4[ri].y * v4[ci].y
                               + p4[ri].z * v4[ci].z + p4[ri].w * v4[ci].w;
        }
        __syncthreads();  // done reading V/P before next tile overwrites
    }

    // finalize: divide by l, zero masked query rows
    #pragma unroll
    for (int ri = 0; ri < 4; ri++) {
        int r = rg * 4 + ri;
        float inv = ((q0 + r) < qlen) ? (1.f / l_i[ri]) : 0.f;
        #pragma unroll
        for (int ci = 0; ci < 4; ci++)
            outp[r * D_MODEL + cg + ci * 16] = o[ri][ci] * inv;
    }
}

// ---------------------------------------------------------------------------
// Inputs (metadata order): Q_seq, K_seq, V_seq, q_len, v_len, WQ, WK, WV
// Output: [B, L, D_MODEL] float32
// ---------------------------------------------------------------------------
extern "C" void kernel_launch(void* const* d_in, const int* in_sizes, int n_in,
                              void* d_out, int out_size)
{
    const float* Q_seq = (const float*)d_in[0];
    const float* K_seq = (const float*)d_in[1];
    const float* V_seq = (const float*)d_in[2];
    const int*   q_len = (const int*)d_in[3];
    const int*   v_len = (const int*)d_in[4];
    const float* WQ    = (const float*)d_in[5];
    const float* WK    = (const float*)d_in[6];
    const float* WV    = (const float*)d_in[7];
    float* out = (float*)d_out;

    dim3 g1(D_MODEL / 128, M_TOT / 128, 3);   // (8, 32, 3)
    proj_gemm<<<g1, 256>>>(Q_seq, K_seq, V_seq, WQ, WK, WV);

    cudaFuncSetAttribute(flash_attn, cudaFuncAttributeMaxDynamicSharedMemorySize, SMEM_BYTES);
    dim3 g2(L_SEQ / 64, NHEAD, BATCH);        // (32, 16, 2)
    flash_attn<<<g2, 256, SMEM_BYTES>>>(q_len, v_len, out);
}

// round 3
// speedup vs baseline: 1.0031x; 1.0031x over previous
#include <cuda_runtime.h>
#include <math.h>

#define D_MODEL 1024
#define L_SEQ   2048
#define BATCH   2
#define NHEAD   16
#define HDIM    64
#define M_TOT   (BATCH * L_SEQ)   // 4096

// Scratch for Q/K/V projections ([B, L, D_MODEL] row-major), 16 MB each.
__device__ float g_q[M_TOT * D_MODEL];
__device__ float g_k[M_TOT * D_MODEL];
__device__ float g_v[M_TOT * D_MODEL];

// ---------------------------------------------------------------------------
// Kernel 1: QKV projection GEMMs.  C[4096,1024] = A[4096,1024] @ W[1024,1024]
// blockIdx.z selects which of the three projections.
// 128x128 block tile, BK=8, 256 threads, 8x8 register microtile.
// ---------------------------------------------------------------------------
__global__ __launch_bounds__(256) void proj_gemm(
    const float* __restrict__ Xq, const float* __restrict__ Xk, const float* __restrict__ Xv,
    const float* __restrict__ Wq, const float* __restrict__ Wk, const float* __restrict__ Wv)
{
    const int GN = D_MODEL, GK = D_MODEL;

    const float* A;
    const float* B;
    float* C;
    if (blockIdx.z == 0)      { A = Xq; B = Wq; C = g_q; }
    else if (blockIdx.z == 1) { A = Xk; B = Wk; C = g_k; }
    else                      { A = Xv; B = Wv; C = g_v; }

    __shared__ float As[8][128];   // transposed A tile: As[k][m]
    __shared__ float Bs[8][128];   // Bs[k][n]

    const int tid  = threadIdx.x;
    const int brow = blockIdx.y * 128;
    const int bcol = blockIdx.x * 128;

    // A tile load: 128 rows x 8 k, one float4 per thread
    const int aRow = tid >> 1;          // 0..127
    const int aCol = (tid & 1) * 4;     // 0 or 4
    // B tile load: 8 k x 128 cols, one float4 per thread
    const int bRow = tid >> 5;          // 0..7
    const int bCol = (tid & 31) * 4;    // 0..124

    const int ty = tid >> 4;            // 0..15  (row microtile group)
    const int tx = tid & 15;            // 0..15  (col microtile group)

    float acc[8][8];
    #pragma unroll
    for (int i = 0; i < 8; i++)
        #pragma unroll
        for (int j = 0; j < 8; j++) acc[i][j] = 0.f;

    for (int k0 = 0; k0 < GK; k0 += 8) {
        float4 a4 = *(const float4*)&A[(brow + aRow) * GK + k0 + aCol];
        As[aCol + 0][aRow] = a4.x;
        As[aCol + 1][aRow] = a4.y;
        As[aCol + 2][aRow] = a4.z;
        As[aCol + 3][aRow] = a4.w;
        *(float4*)&Bs[bRow][bCol] = *(const float4*)&B[(k0 + bRow) * GN + bcol + bCol];
        __syncthreads();

        #pragma unroll
        for (int k = 0; k < 8; k++) {
            float ar[8], br[8];
            *(float4*)&ar[0] = *(const float4*)&As[k][ty * 8];
            *(float4*)&ar[4] = *(const float4*)&As[k][ty * 8 + 4];
            *(float4*)&br[0] = *(const float4*)&Bs[k][tx * 8];
            *(float4*)&br[4] = *(const float4*)&Bs[k][tx * 8 + 4];
            #pragma unroll
            for (int i = 0; i < 8; i++)
                #pragma unroll
                for (int j = 0; j < 8; j++)
                    acc[i][j] += ar[i] * br[j];
        }
        __syncthreads();
    }

    #pragma unroll
    for (int i = 0; i < 8; i++) {
        int r = brow + ty * 8 + i;
        *(float4*)&C[r * GN + bcol + tx * 8]     = make_float4(acc[i][0], acc[i][1], acc[i][2], acc[i][3]);
        *(float4*)&C[r * GN + bcol + tx * 8 + 4] = make_float4(acc[i][4], acc[i][5], acc[i][6], acc[i][7]);
    }
}

// ---------------------------------------------------------------------------
// Kernel 2: flash attention per (q-tile of 64, head, batch).
// Online softmax, kv loop bounded by v_len (exactly equivalent to the -1e12
// additive mask: exp underflows to 0 in fp32). Query rows >= q_len output 0.
// 256 threads: thread (rg, cg) owns rows rg*4..+3 and cols {cg + 16*ci}.
// ---------------------------------------------------------------------------
#define PAD 68
#define SMEM_FLOATS (3 * 64 * PAD)
#define SMEM_BYTES  (SMEM_FLOATS * 4)

__global__ __launch_bounds__(256) void flash_attn(
    const int* __restrict__ q_len, const int* __restrict__ v_len,
    float* __restrict__ out)
{
    const int qt = blockIdx.x;   // 0..31
    const int h  = blockIdx.y;   // 0..15
    const int b  = blockIdx.z;   // 0..1
    const int q0 = qt * 64;
    const int tid = threadIdx.x;

    const int qlen = q_len[b];
    const int klen = v_len[b];

    float* outp = out + (b * L_SEQ + q0) * D_MODEL + h * HDIM;

    if (q0 >= qlen) {
        // whole q tile masked: write zeros
        for (int idx = tid; idx < 64 * 16; idx += 256) {
            int r = idx >> 4, c4 = (idx & 15) << 2;
            *(float4*)&outp[r * D_MODEL + c4] = make_float4(0.f, 0.f, 0.f, 0.f);
        }
        return;
    }

    extern __shared__ float sm[];
    float* Qs  = sm;                 // 64 x PAD (Q rows, scaled)
    float* KVs = sm + 64 * PAD;      // 64 x PAD (K rows, then V transposed [d][j])
    float* Ps  = sm + 2 * 64 * PAD;  // 64 x PAD (probabilities)

    const float* qp = g_q + (b * L_SEQ + q0) * D_MODEL + h * HDIM;
    const float* kp = g_k + (b * L_SEQ) * D_MODEL + h * HDIM;
    const float* vp = g_v + (b * L_SEQ) * D_MODEL + h * HDIM;

    // Load and scale Q tile (64x64)
    for (int idx = tid; idx < 64 * 16; idx += 256) {
        int r = idx >> 4, c4 = (idx & 15) << 2;
        float4 v4 = *(const float4*)&qp[r * D_MODEL + c4];
        v4.x *= 0.125f; v4.y *= 0.125f; v4.z *= 0.125f; v4.w *= 0.125f;
        *(float4*)&Qs[r * PAD + c4] = v4;
    }

    const int rg = tid >> 4;   // 0..15
    const int cg = tid & 15;   // 0..15

    float m_i[4], l_i[4], o[4][4];
    #pragma unroll
    for (int i = 0; i < 4; i++) {
        m_i[i] = -1e30f; l_i[i] = 0.f;
        #pragma unroll
        for (int j = 0; j < 4; j++) o[i][j] = 0.f;
    }

    const int n_kv = (klen + 63) >> 6;
    for (int kt = 0; kt < n_kv; kt++) {
        const int k0 = kt << 6;

        // Load K tile (row-major [j][d])
        for (int idx = tid; idx < 64 * 16; idx += 256) {
            int r = idx >> 4, c4 = (idx & 15) << 2;
            *(float4*)&KVs[r * PAD + c4] = *(const float4*)&kp[(k0 + r) * D_MODEL + c4];
        }
        __syncthreads();

        // S = Q K^T for this thread's 4x4 patch
        float s[4][4];
        #pragma unroll
        for (int i = 0; i < 4; i++)
            #pragma unroll
            for (int j = 0; j < 4; j++) s[i][j] = 0.f;

        #pragma unroll
        for (int d4 = 0; d4 < 16; d4++) {
            float4 q4[4], k4[4];
            #pragma unroll
            for (int ri = 0; ri < 4; ri++)
                q4[ri] = *(const float4*)&Qs[(rg * 4 + ri) * PAD + d4 * 4];
            #pragma unroll
            for (int ci = 0; ci < 4; ci++)
                k4[ci] = *(const float4*)&KVs[(cg + ci * 16) * PAD + d4 * 4];
            #pragma unroll
            for (int ri = 0; ri < 4; ri++)
                #pragma unroll
                for (int ci = 0; ci < 4; ci++)
                    s[ri][ci] += q4[ri].x * k4[ci].x + q4[ri].y * k4[ci].y
                               + q4[ri].z * k4[ci].z + q4[ri].w * k4[ci].w;
        }

        // key mask for the boundary tile
        #pragma unroll
        for (int ci = 0; ci < 4; ci++) {
            if (k0 + cg + ci * 16 >= klen) {
                #pragma unroll
                for (int ri = 0; ri < 4; ri++) s[ri][ci] = -1e30f;
            }
        }

        // online softmax per row (16 threads per row cooperate via shfl)
        #pragma unroll
        for (int ri = 0; ri < 4; ri++) {
            float mx = fmaxf(fmaxf(s[ri][0], s[ri][1]), fmaxf(s[ri][2], s[ri][3]));
            #pragma unroll
            for (int off = 1; off < 16; off <<= 1)
                mx = fmaxf(mx, __shfl_xor_sync(0xffffffffu, mx, off));

            float m_new = fmaxf(m_i[ri], mx);
            float scale = __expf(m_i[ri] - m_new);

            float rsum = 0.f;
            #pragma unroll
            for (int ci = 0; ci < 4; ci++) {
                float p = __expf(s[ri][ci] - m_new);
                rsum += p;
                Ps[(rg * 4 + ri) * PAD + cg + ci * 16] = p;
            }
            #pragma unroll
            for (int off = 1; off < 16; off <<= 1)
                rsum += __shfl_xor_sync(0xffffffffu, rsum, off);

            l_i[ri] = l_i[ri] * scale + rsum;
            m_i[ri] = m_new;
            #pragma unroll
            for (int ci = 0; ci < 4; ci++) o[ri][ci] *= scale;
        }
        __syncthreads();  // done reading K tile; Ps visible

        // Load V tile transposed into KVs: KVs[d][j]
        for (int idx = tid; idx < 64 * 16; idx += 256) {
            int r = idx >> 4, c4 = (idx & 15) << 2;
            float4 v4 = *(const float4*)&vp[(k0 + r) * D_MODEL + c4];
            KVs[(c4 + 0) * PAD + r] = v4.x;
            KVs[(c4 + 1) * PAD + r] = v4.y;
            KVs[(c4 + 2) * PAD + r] = v4.z;
            KVs[(c4 + 3) * PAD + r] = v4.w;
        }
        __syncthreads();

        // O += P @ V  (vectorized over j via the transposed V)
        #pragma unroll
        for (int j4 = 0; j4 < 16; j4++) {
            float4 p4[4], v4[4];
            #pragma unroll
            for (int ri = 0; ri < 4; ri++)
                p4[ri] = *(const float4*)&Ps[(rg * 4 + ri) * PAD + j4 * 4];
            #pragma unroll
            for (int ci = 0; ci < 4; ci++)
                v4[ci] = *(const float4*)&KVs[(cg + ci * 16) * PAD + j4 * 4];
            #pragma unroll
            for (int ri = 0; ri < 4; ri++)
                #pragma unroll
                for (int ci = 0; ci < 4; ci++)
                    o[ri][ci] += p4[ri].x * v4[ci].x + p4[ri].y * v4[ci].y
                               + p4[ri].z * v4[ci].z + p4[ri].w * v4[ci].w;
        }
        __syncthreads();  // done reading V/P before next tile overwrites
    }

    // finalize: divide by l, zero masked query rows
    #pragma unroll
    for (int ri = 0; ri < 4; ri++) {
        int r = rg * 4 + ri;
        float inv = ((q0 + r) < qlen) ? (1.f / l_i[ri]) : 0.f;
        #pragma unroll
        for (int ci = 0; ci < 4; ci++)
            outp[r * D_MODEL + cg + ci * 16] = o[ri][ci] * inv;
    }
}

// ---------------------------------------------------------------------------
// Inputs (metadata order): Q_seq, K_seq, V_seq, q_len, v_len, WQ, WK, WV
// Output: [B, L, D_MODEL] float32
// ---------------------------------------------------------------------------
extern "C" void kernel_launch(void* const* d_in, const int* in_sizes, int n_in,
                              void* d_out, int out_size)
{
    const float* Q_seq = (const float*)d_in[0];
    const float* K_seq = (const float*)d_in[1];
    const float* V_seq = (const float*)d_in[2];
    const int*   q_len = (const int*)d_in[3];
    const int*   v_len = (const int*)d_in[4];
    const float* WQ    = (const float*)d_in[5];
    const float* WK    = (const float*)d_in[6];
    const float* WV    = (const float*)d_in[7];
    float* out = (float*)d_out;

    dim3 g1(D_MODEL / 128, M_TOT / 128, 3);   // (8, 32, 3)
    proj_gemm<<<g1, 256>>>(Q_seq, K_seq, V_seq, WQ, WK, WV);

    cudaFuncSetAttribute(flash_attn, cudaFuncAttributeMaxDynamicSharedMemorySize, SMEM_BYTES);
    dim3 g2(L_SEQ / 64, NHEAD, BATCH);        // (32, 16, 2)
    flash_attn<<<g2, 256, SMEM_BYTES>>>(q_len, v_len, out);
}

// round 4
// speedup vs baseline: 1.0034x; 1.0003x over previous
#include <cuda_runtime.h>
#include <math.h>

#define D_MODEL 1024
#define L_SEQ   2048
#define BATCH   2
#define NHEAD   16
#define HDIM    64
#define M_TOT   (BATCH * L_SEQ)   // 4096

// Scratch for Q/K/V projections ([B, L, D_MODEL] row-major), 16 MB each.
__device__ float g_q[M_TOT * D_MODEL];
__device__ float g_k[M_TOT * D_MODEL];
__device__ float g_v[M_TOT * D_MODEL];

// ---------------------------------------------------------------------------
// Kernel 1: QKV projection GEMMs.  C[4096,1024] = A[4096,1024] @ W[1024,1024]
// blockIdx.z selects which of the three projections.
// 128x128 block tile, BK=8, 256 threads, 8x8 register microtile.
// ---------------------------------------------------------------------------
__global__ __launch_bounds__(256) void proj_gemm(
    const float* __restrict__ Xq, const float* __restrict__ Xk, const float* __restrict__ Xv,
    const float* __restrict__ Wq, const float* __restrict__ Wk, const float* __restrict__ Wv)
{
    const int GN = D_MODEL, GK = D_MODEL;

    const float* A;
    const float* B;
    float* C;
    if (blockIdx.z == 0)      { A = Xq; B = Wq; C = g_q; }
    else if (blockIdx.z == 1) { A = Xk; B = Wk; C = g_k; }
    else                      { A = Xv; B = Wv; C = g_v; }

    __shared__ float As[8][128];   // transposed A tile: As[k][m]
    __shared__ float Bs[8][128];   // Bs[k][n]

    const int tid  = threadIdx.x;
    const int brow = blockIdx.y * 128;
    const int bcol = blockIdx.x * 128;

    // A tile load: 128 rows x 8 k, one float4 per thread
    const int aRow = tid >> 1;          // 0..127
    const int aCol = (tid & 1) * 4;     // 0 or 4
    // B tile load: 8 k x 128 cols, one float4 per thread
    const int bRow = tid >> 5;          // 0..7
    const int bCol = (tid & 31) * 4;    // 0..124

    const int ty = tid >> 4;            // 0..15  (row microtile group)
    const int tx = tid & 15;            // 0..15  (col microtile group)

    float acc[8][8];
    #pragma unroll
    for (int i = 0; i < 8; i++)
        #pragma unroll
        for (int j = 0; j < 8; j++) acc[i][j] = 0.f;

    for (int k0 = 0; k0 < GK; k0 += 8) {
        float4 a4 = *(const float4*)&A[(brow + aRow) * GK + k0 + aCol];
        As[aCol + 0][aRow] = a4.x;
        As[aCol + 1][aRow] = a4.y;
        As[aCol + 2][aRow] = a4.z;
        As[aCol + 3][aRow] = a4.w;
        *(float4*)&Bs[bRow][bCol] = *(const float4*)&B[(k0 + bRow) * GN + bcol + bCol];
        __syncthreads();

        #pragma unroll
        for (int k = 0; k < 8; k++) {
            float ar[8], br[8];
            *(float4*)&ar[0] = *(const float4*)&As[k][ty * 8];
            *(float4*)&ar[4] = *(const float4*)&As[k][ty * 8 + 4];
            *(float4*)&br[0] = *(const float4*)&Bs[k][tx * 8];
            *(float4*)&br[4] = *(const float4*)&Bs[k][tx * 8 + 4];
            #pragma unroll
            for (int i = 0; i < 8; i++)
                #pragma unroll
                for (int j = 0; j < 8; j++)
                    acc[i][j] += ar[i] * br[j];
        }
        __syncthreads();
    }

    #pragma unroll
    for (int i = 0; i < 8; i++) {
        int r = brow + ty * 8 + i;
        *(float4*)&C[r * GN + bcol + tx * 8]     = make_float4(acc[i][0], acc[i][1], acc[i][2], acc[i][3]);
        *(float4*)&C[r * GN + bcol + tx * 8 + 4] = make_float4(acc[i][4], acc[i][5], acc[i][6], acc[i][7]);
    }
}

// ---------------------------------------------------------------------------
// Kernel 2: flash attention per (q-tile of 64, head, batch).
// Online softmax, kv loop bounded by v_len (exactly equivalent to the -1e12
// additive mask: exp underflows to 0 in fp32). Query rows >= q_len output 0.
// 256 threads: thread (rg, cg) owns rows rg*4..+3 and cols {cg + 16*ci}.
// ---------------------------------------------------------------------------
#define PAD 68
#define SMEM_FLOATS (3 * 64 * PAD)
#define SMEM_BYTES  (SMEM_FLOATS * 4)

__global__ __launch_bounds__(256) void flash_attn(
    const int* __restrict__ q_len, const int* __restrict__ v_len,
    float* __restrict__ out)
{
    const int qt = blockIdx.x;   // 0..31
    const int h  = blockIdx.y;   // 0..15
    const int b  = blockIdx.z;   // 0..1
    const int q0 = qt * 64;
    const int tid = threadIdx.x;

    const int qlen = q_len[b];
    const int klen = v_len[b];

    float* outp = out + (b * L_SEQ + q0) * D_MODEL + h * HDIM;

    if (q0 >= qlen) {
        // whole q tile masked: write zeros
        for (int idx = tid; idx < 64 * 16; idx += 256) {
            int r = idx >> 4, c4 = (idx & 15) << 2;
            *(float4*)&outp[r * D_MODEL + c4] = make_float4(0.f, 0.f, 0.f, 0.f);
        }
        return;
    }

    extern __shared__ float sm[];
    float* Qs  = sm;                 // 64 x PAD (Q rows, scaled)
    float* KVs = sm + 64 * PAD;      // 64 x PAD (K rows, then V transposed [d][j])
    float* Ps  = sm + 2 * 64 * PAD;  // 64 x PAD (probabilities)

    const float* qp = g_q + (b * L_SEQ + q0) * D_MODEL + h * HDIM;
    const float* kp = g_k + (b * L_SEQ) * D_MODEL + h * HDIM;
    const float* vp = g_v + (b * L_SEQ) * D_MODEL + h * HDIM;

    // Load and scale Q tile (64x64)
    for (int idx = tid; idx < 64 * 16; idx += 256) {
        int r = idx >> 4, c4 = (idx & 15) << 2;
        float4 v4 = *(const float4*)&qp[r * D_MODEL + c4];
        v4.x *= 0.125f; v4.y *= 0.125f; v4.z *= 0.125f; v4.w *= 0.125f;
        *(float4*)&Qs[r * PAD + c4] = v4;
    }

    const int rg = tid >> 4;   // 0..15
    const int cg = tid & 15;   // 0..15

    float m_i[4], l_i[4], o[4][4];
    #pragma unroll
    for (int i = 0; i < 4; i++) {
        m_i[i] = -1e30f; l_i[i] = 0.f;
        #pragma unroll
        for (int j = 0; j < 4; j++) o[i][j] = 0.f;
    }

    const int n_kv = (klen + 63) >> 6;
    for (int kt = 0; kt < n_kv; kt++) {
        const int k0 = kt << 6;

        // Load K tile (row-major [j][d])
        for (int idx = tid; idx < 64 * 16; idx += 256) {
            int r = idx >> 4, c4 = (idx & 15) << 2;
            *(float4*)&KVs[r * PAD + c4] = *(const float4*)&kp[(k0 + r) * D_MODEL + c4];
        }
        __syncthreads();

        // S = Q K^T for this thread's 4x4 patch
        float s[4][4];
        #pragma unroll
        for (int i = 0; i < 4; i++)
            #pragma unroll
            for (int j = 0; j < 4; j++) s[i][j] = 0.f;

        #pragma unroll
        for (int d4 = 0; d4 < 16; d4++) {
            float4 q4[4], k4[4];
            #pragma unroll
            for (int ri = 0; ri < 4; ri++)
                q4[ri] = *(const float4*)&Qs[(rg * 4 + ri) * PAD + d4 * 4];
            #pragma unroll
            for (int ci = 0; ci < 4; ci++)
                k4[ci] = *(const float4*)&KVs[(cg + ci * 16) * PAD + d4 * 4];
            #pragma unroll
            for (int ri = 0; ri < 4; ri++)
                #pragma unroll
                for (int ci = 0; ci < 4; ci++)
                    s[ri][ci] += q4[ri].x * k4[ci].x + q4[ri].y * k4[ci].y
                               + q4[ri].z * k4[ci].z + q4[ri].w * k4[ci].w;
        }

        // key mask for the boundary tile
        #pragma unroll
        for (int ci = 0; ci < 4; ci++) {
            if (k0 + cg + ci * 16 >= klen) {
                #pragma unroll
                for (int ri = 0; ri < 4; ri++) s[ri][ci] = -1e30f;
            }
        }

        // online softmax per row (16 threads per row cooperate via shfl)
        #pragma unroll
        for (int ri = 0; ri < 4; ri++) {
            float mx = fmaxf(fmaxf(s[ri][0], s[ri][1]), fmaxf(s[ri][2], s[ri][3]));
            #pragma unroll
            for (int off = 1; off < 16; off <<= 1)
                mx = fmaxf(mx, __shfl_xor_sync(0xffffffffu, mx, off));

            float m_new = fmaxf(m_i[ri], mx);
            float scale = __expf(m_i[ri] - m_new);

            float rsum = 0.f;
            #pragma unroll
            for (int ci = 0; ci < 4; ci++) {
                float p = __expf(s[ri][ci] - m_new);
                rsum += p;
                Ps[(rg * 4 + ri) * PAD + cg + ci * 16] = p;
            }
            #pragma unroll
            for (int off = 1; off < 16; off <<= 1)
                rsum += __shfl_xor_sync(0xffffffffu, rsum, off);

            l_i[ri] = l_i[ri] * scale + rsum;
            m_i[ri] = m_new;
            #pragma unroll
            for (int ci = 0; ci < 4; ci++) o[ri][ci] *= scale;
        }
        __syncthreads();  // done reading K tile; Ps visible

        // Load V tile transposed into KVs: KVs[d][j]
        for (int idx = tid; idx < 64 * 16; idx += 256) {
            int r = idx >> 4, c4 = (idx & 15) << 2;
            float4 v4 = *(const float4*)&vp[(k0 + r) * D_MODEL + c4];
            KVs[(c4 + 0) * PAD + r] = v4.x;
            KVs[(c4 + 1) * PAD + r] = v4.y;
            KVs[(c4 + 2) * PAD + r] = v4.z;
            KVs[(c4 + 3) * PAD + r] = v4.w;
        }
        __syncthreads();

        // O += P @ V  (vectorized over j via the transposed V)
        #pragma unroll
        for (int j4 = 0; j4 < 16; j4++) {
            float4 p4[4], v4[4];
            #pragma unroll
            for (int ri = 0; ri < 4; ri++)
                p4[ri] = *(const float4*)&Ps[(rg * 4 + ri) * PAD + j4 * 4];
            #pragma unroll
            for (int ci = 0; ci < 4; ci++)
                v4[ci] = *(const float4*)&KVs[(cg + ci * 16) * PAD + j4 * 4];
            #pragma unroll
            for (int ri = 0; ri < 4; ri++)
                #pragma unroll
                for (int ci = 0; ci < 4; ci++)
                    o[ri][ci] += p4[ri].x * v4[ci].x + p4[ri].y * v4[ci].y
                               + p4[ri].z * v4[ci].z + p4[ri].w * v4[ci].w;
        }
        __syncthreads();  // done reading V/P before next tile overwrites
    }

    // finalize: divide by l, zero masked query rows
    #pragma unroll
    for (int ri = 0; ri < 4; ri++) {
        int r = rg * 4 + ri;
        float inv = ((q0 + r) < qlen) ? (1.f / l_i[ri]) : 0.f;
        #pragma unroll
        for (int ci = 0; ci < 4; ci++)
            outp[r * D_MODEL + cg + ci * 16] = o[ri][ci] * inv;
    }
}

// ---------------------------------------------------------------------------
// Inputs (metadata order): Q_seq, K_seq, V_seq, q_len, v_len, WQ, WK, WV
// Output: [B, L, D_MODEL] float32
// ---------------------------------------------------------------------------
extern "C" void kernel_launch(void* const* d_in, const int* in_sizes, int n_in,
                              void* d_out, int out_size)
{
    const float* Q_seq = (const float*)d_in[0];
    const float* K_seq = (const float*)d_in[1];
    const float* V_seq = (const float*)d_in[2];
    const int*   q_len = (const int*)d_in[3];
    const int*   v_len = (const int*)d_in[4];
    const float* WQ    = (const float*)d_in[5];
    const float* WK    = (const float*)d_in[6];
    const float* WV    = (const float*)d_in[7];
    float* out = (float*)d_out;

    dim3 g1(D_MODEL / 128, M_TOT / 128, 3);   // (8, 32, 3)
    proj_gemm<<<g1, 256>>>(Q_seq, K_seq, V_seq, WQ, WK, WV);

    cudaFuncSetAttribute(flash_attn, cudaFuncAttributeMaxDynamicSharedMemorySize, SMEM_BYTES);
    dim3 g2(L_SEQ / 64, NHEAD, BATCH);        // (32, 16, 2)
    flash_attn<<<g2, 256, SMEM_BYTES>>>(q_len, v_len, out);
}

// round 5
// speedup vs baseline: 1.0042x; 1.0009x over previous
#include <cuda_runtime.h>
#include <math.h>

#define D_MODEL 1024
#define L_SEQ   2048
#define BATCH   2
#define NHEAD   16
#define HDIM    64
#define M_TOT   (BATCH * L_SEQ)   // 4096

// Scratch for Q/K/V projections ([B, L, D_MODEL] row-major), 16 MB each.
__device__ float g_q[M_TOT * D_MODEL];
__device__ float g_k[M_TOT * D_MODEL];
__device__ float g_v[M_TOT * D_MODEL];

// ---------------------------------------------------------------------------
// Kernel 1: QKV projection GEMMs.  C[4096,1024] = A[4096,1024] @ W[1024,1024]
// blockIdx.z selects which of the three projections.
// 128x128 block tile, BK=8, 256 threads, 8x8 register microtile.
// ---------------------------------------------------------------------------
__global__ __launch_bounds__(256) void proj_gemm(
    const float* __restrict__ Xq, const float* __restrict__ Xk, const float* __restrict__ Xv,
    const float* __restrict__ Wq, const float* __restrict__ Wk, const float* __restrict__ Wv)
{
    const int GN = D_MODEL, GK = D_MODEL;

    const float* A;
    const float* B;
    float* C;
    if (blockIdx.z == 0)      { A = Xq; B = Wq; C = g_q; }
    else if (blockIdx.z == 1) { A = Xk; B = Wk; C = g_k; }
    else                      { A = Xv; B = Wv; C = g_v; }

    __shared__ float As[8][128];   // transposed A tile: As[k][m]
    __shared__ float Bs[8][128];   // Bs[k][n]

    const int tid  = threadIdx.x;
    const int brow = blockIdx.y * 128;
    const int bcol = blockIdx.x * 128;

    // A tile load: 128 rows x 8 k, one float4 per thread
    const int aRow = tid >> 1;          // 0..127
    const int aCol = (tid & 1) * 4;     // 0 or 4
    // B tile load: 8 k x 128 cols, one float4 per thread
    const int bRow = tid >> 5;          // 0..7
    const int bCol = (tid & 31) * 4;    // 0..124

    const int ty = tid >> 4;            // 0..15  (row microtile group)
    const int tx = tid & 15;            // 0..15  (col microtile group)

    float acc[8][8];
    #pragma unroll
    for (int i = 0; i < 8; i++)
        #pragma unroll
        for (int j = 0; j < 8; j++) acc[i][j] = 0.f;

    for (int k0 = 0; k0 < GK; k0 += 8) {
        float4 a4 = *(const float4*)&A[(brow + aRow) * GK + k0 + aCol];
        As[aCol + 0][aRow] = a4.x;
        As[aCol + 1][aRow] = a4.y;
        As[aCol + 2][aRow] = a4.z;
        As[aCol + 3][aRow] = a4.w;
        *(float4*)&Bs[bRow][bCol] = *(const float4*)&B[(k0 + bRow) * GN + bcol + bCol];
        __syncthreads();

        #pragma unroll
        for (int k = 0; k < 8; k++) {
            float ar[8], br[8];
            *(float4*)&ar[0] = *(const float4*)&As[k][ty * 8];
            *(float4*)&ar[4] = *(const float4*)&As[k][ty * 8 + 4];
            *(float4*)&br[0] = *(const float4*)&Bs[k][tx * 8];
            *(float4*)&br[4] = *(const float4*)&Bs[k][tx * 8 + 4];
            #pragma unroll
            for (int i = 0; i < 8; i++)
                #pragma unroll
                for (int j = 0; j < 8; j++)
                    acc[i][j] += ar[i] * br[j];
        }
        __syncthreads();
    }

    #pragma unroll
    for (int i = 0; i < 8; i++) {
        int r = brow + ty * 8 + i;
        *(float4*)&C[r * GN + bcol + tx * 8]     = make_float4(acc[i][0], acc[i][1], acc[i][2], acc[i][3]);
        *(float4*)&C[r * GN + bcol + tx * 8 + 4] = make_float4(acc[i][4], acc[i][5], acc[i][6], acc[i][7]);
    }
}

// ---------------------------------------------------------------------------
// Kernel 2: flash attention per (q-tile of 64, head, batch).
// Online softmax, kv loop bounded by v_len (exactly equivalent to the -1e12
// additive mask: exp underflows to 0 in fp32). Query rows >= q_len output 0.
// 256 threads: thread (rg, cg) owns rows rg*4..+3 and cols {cg + 16*ci}.
// ---------------------------------------------------------------------------
#define PAD 68
#define SMEM_FLOATS (3 * 64 * PAD)
#define SMEM_BYTES  (SMEM_FLOATS * 4)

__global__ __launch_bounds__(256) void flash_attn(
    const int* __restrict__ q_len, const int* __restrict__ v_len,
    float* __restrict__ out)
{
    const int qt = blockIdx.x;   // 0..31
    const int h  = blockIdx.y;   // 0..15
    const int b  = blockIdx.z;   // 0..1
    const int q0 = qt * 64;
    const int tid = threadIdx.x;

    const int qlen = q_len[b];
    const int klen = v_len[b];

    float* outp = out + (b * L_SEQ + q0) * D_MODEL + h * HDIM;

    if (q0 >= qlen) {
        // whole q tile masked: write zeros
        for (int idx = tid; idx < 64 * 16; idx += 256) {
            int r = idx >> 4, c4 = (idx & 15) << 2;
            *(float4*)&outp[r * D_MODEL + c4] = make_float4(0.f, 0.f, 0.f, 0.f);
        }
        return;
    }

    extern __shared__ float sm[];
    float* Qs  = sm;                 // 64 x PAD (Q rows, scaled)
    float* KVs = sm + 64 * PAD;      // 64 x PAD (K rows, then V transposed [d][j])
    float* Ps  = sm + 2 * 64 * PAD;  // 64 x PAD (probabilities)

    const float* qp = g_q + (b * L_SEQ + q0) * D_MODEL + h * HDIM;
    const float* kp = g_k + (b * L_SEQ) * D_MODEL + h * HDIM;
    const float* vp = g_v + (b * L_SEQ) * D_MODEL + h * HDIM;

    // Load and scale Q tile (64x64)
    for (int idx = tid; idx < 64 * 16; idx += 256) {
        int r = idx >> 4, c4 = (idx & 15) << 2;
        float4 v4 = *(const float4*)&qp[r * D_MODEL + c4];
        v4.x *= 0.125f; v4.y *= 0.125f; v4.z *= 0.125f; v4.w *= 0.125f;
        *(float4*)&Qs[r * PAD + c4] = v4;
    }

    const int rg = tid >> 4;   // 0..15
    const int cg = tid & 15;   // 0..15

    float m_i[4], l_i[4], o[4][4];
    #pragma unroll
    for (int i = 0; i < 4; i++) {
        m_i[i] = -1e30f; l_i[i] = 0.f;
        #pragma unroll
        for (int j = 0; j < 4; j++) o[i][j] = 0.f;
    }

    const int n_kv = (klen + 63) >> 6;
    for (int kt = 0; kt < n_kv; kt++) {
        const int k0 = kt << 6;

        // Load K tile (row-major [j][d])
        for (int idx = tid; idx < 64 * 16; idx += 256) {
            int r = idx >> 4, c4 = (idx & 15) << 2;
            *(float4*)&KVs[r * PAD + c4] = *(const float4*)&kp[(k0 + r) * D_MODEL + c4];
        }
        __syncthreads();

        // S = Q K^T for this thread's 4x4 patch
        float s[4][4];
        #pragma unroll
        for (int i = 0; i < 4; i++)
            #pragma unroll
            for (int j = 0; j < 4; j++) s[i][j] = 0.f;

        #pragma unroll
        for (int d4 = 0; d4 < 16; d4++) {
            float4 q4[4], k4[4];
            #pragma unroll
            for (int ri = 0; ri < 4; ri++)
                q4[ri] = *(const float4*)&Qs[(rg * 4 + ri) * PAD + d4 * 4];
            #pragma unroll
            for (int ci = 0; ci < 4; ci++)
                k4[ci] = *(const float4*)&KVs[(cg + ci * 16) * PAD + d4 * 4];
            #pragma unroll
            for (int ri = 0; ri < 4; ri++)
                #pragma unroll
                for (int ci = 0; ci < 4; ci++)
                    s[ri][ci] += q4[ri].x * k4[ci].x + q4[ri].y * k4[ci].y
                               + q4[ri].z * k4[ci].z + q4[ri].w * k4[ci].w;
        }

        // key mask for the boundary tile
        #pragma unroll
        for (int ci = 0; ci < 4; ci++) {
            if (k0 + cg + ci * 16 >= klen) {
                #pragma unroll
                for (int ri = 0; ri < 4; ri++) s[ri][ci] = -1e30f;
            }
        }

        // online softmax per row (16 threads per row cooperate via shfl)
        #pragma unroll
        for (int ri = 0; ri < 4; ri++) {
            float mx = fmaxf(fmaxf(s[ri][0], s[ri][1]), fmaxf(s[ri][2], s[ri][3]));
            #pragma unroll
            for (int off = 1; off < 16; off <<= 1)
                mx = fmaxf(mx, __shfl_xor_sync(0xffffffffu, mx, off));

            float m_new = fmaxf(m_i[ri], mx);
            float scale = __expf(m_i[ri] - m_new);

            float rsum = 0.f;
            #pragma unroll
            for (int ci = 0; ci < 4; ci++) {
                float p = __expf(s[ri][ci] - m_new);
                rsum += p;
                Ps[(rg * 4 + ri) * PAD + cg + ci * 16] = p;
            }
            #pragma unroll
            for (int off = 1; off < 16; off <<= 1)
                rsum += __shfl_xor_sync(0xffffffffu, rsum, off);

            l_i[ri] = l_i[ri] * scale + rsum;
            m_i[ri] = m_new;
            #pragma unroll
            for (int ci = 0; ci < 4; ci++) o[ri][ci] *= scale;
        }
        __syncthreads();  // done reading K tile; Ps visible

        // Load V tile transposed into KVs: KVs[d][j]
        for (int idx = tid; idx < 64 * 16; idx += 256) {
            int r = idx >> 4, c4 = (idx & 15) << 2;
            float4 v4 = *(const float4*)&vp[(k0 + r) * D_MODEL + c4];
            KVs[(c4 + 0) * PAD + r] = v4.x;
            KVs[(c4 + 1) * PAD + r] = v4.y;
            KVs[(c4 + 2) * PAD + r] = v4.z;
            KVs[(c4 + 3) * PAD + r] = v4.w;
        }
        __syncthreads();

        // O += P @ V  (vectorized over j via the transposed V)
        #pragma unroll
        for (int j4 = 0; j4 < 16; j4++) {
            float4 p4[4], v4[4];
            #pragma unroll
            for (int ri = 0; ri < 4; ri++)
                p4[ri] = *(const float4*)&Ps[(rg * 4 + ri) * PAD + j4 * 4];
            #pragma unroll
            for (int ci = 0; ci < 4; ci++)
                v4[ci] = *(const float4*)&KVs[(cg + ci * 16) * PAD + j4 * 4];
            #pragma unroll
            for (int ri = 0; ri < 4; ri++)
                #pragma unroll
                for (int ci = 0; ci < 4; ci++)
                    o[ri][ci] += p4[ri].x * v4[ci].x + p4[ri].y * v4[ci].y
                               + p4[ri].z * v4[ci].z + p4[ri].w * v4[ci].w;
        }
        __syncthreads();  // done reading V/P before next tile overwrites
    }

    // finalize: divide by l, zero masked query rows
    #pragma unroll
    for (int ri = 0; ri < 4; ri++) {
        int r = rg * 4 + ri;
        float inv = ((q0 + r) < qlen) ? (1.f / l_i[ri]) : 0.f;
        #pragma unroll
        for (int ci = 0; ci < 4; ci++)
            outp[r * D_MODEL + cg + ci * 16] = o[ri][ci] * inv;
    }
}

// ---------------------------------------------------------------------------
// Inputs (metadata order): Q_seq, K_seq, V_seq, q_len, v_len, WQ, WK, WV
// Output: [B, L, D_MODEL] float32
// ---------------------------------------------------------------------------
extern "C" void kernel_launch(void* const* d_in, const int* in_sizes, int n_in,
                              void* d_out, int out_size)
{
    const float* Q_seq = (const float*)d_in[0];
    const float* K_seq = (const float*)d_in[1];
    const float* V_seq = (const float*)d_in[2];
    const int*   q_len = (const int*)d_in[3];
    const int*   v_len = (const int*)d_in[4];
    const float* WQ    = (const float*)d_in[5];
    const float* WK    = (const float*)d_in[6];
    const float* WV    = (const float*)d_in[7];
    float* out = (float*)d_out;

    dim3 g1(D_MODEL / 128, M_TOT / 128, 3);   // (8, 32, 3)
    proj_gemm<<<g1, 256>>>(Q_seq, K_seq, V_seq, WQ, WK, WV);

    cudaFuncSetAttribute(flash_attn, cudaFuncAttributeMaxDynamicSharedMemorySize, SMEM_BYTES);
    dim3 g2(L_SEQ / 64, NHEAD, BATCH);        // (32, 16, 2)
    flash_attn<<<g2, 256, SMEM_BYTES>>>(q_len, v_len, out);
}